// round 1
// baseline (speedup 1.0000x reference)
#include <cuda_runtime.h>
#include <cuda_bf16.h>
#include <cstdint>

// Problem constants (fixed shapes from the reference)
#define B_   2
#define N_   2048
#define C_   1024
#define H_   16
#define HD_  64
#define MTOT (B_ * N_)          // 4096
#define QKV_COLS (3 * C_)       // 3072
#define LORA_R 4
#define LORA_SCALE 0.25f

// ---------------------------------------------------------------------------
// Scratch (static device globals -> no allocation, graph-capturable)
// ---------------------------------------------------------------------------
__device__ float g_qkv[(size_t)MTOT * QKV_COLS];   // 50.3 MB
__device__ float g_attn[(size_t)MTOT * C_];        // 16.8 MB
__device__ float g_la[(size_t)MTOT * 8];           // 128 KB

// ---------------------------------------------------------------------------
// Kernel 1: lora activations  la[m][r] = sum_k x[m][k] * lora_A[r][k]
// one warp per row, 8 outputs per row
// ---------------------------------------------------------------------------
__global__ __launch_bounds__(256) void lora_a_kernel(
    const float* __restrict__ x,       // [MTOT, C]
    const float* __restrict__ la_w,    // [8, C]
    float* __restrict__ la)            // [MTOT, 8]
{
    int warp = threadIdx.x >> 5;
    int lane = threadIdx.x & 31;
    int row  = blockIdx.x * 8 + warp;
    if (row >= MTOT) return;
    const float* xr = x + (size_t)row * C_;
    float acc[8] = {0.f,0.f,0.f,0.f,0.f,0.f,0.f,0.f};
    for (int k = lane; k < C_; k += 32) {
        float xv = xr[k];
        #pragma unroll
        for (int r = 0; r < 8; r++) acc[r] += xv * la_w[r * C_ + k];
    }
    #pragma unroll
    for (int r = 0; r < 8; r++) {
        #pragma unroll
        for (int off = 16; off; off >>= 1)
            acc[r] += __shfl_xor_sync(0xffffffffu, acc[r], off);
    }
    if (lane == 0) {
        float* out = la + (size_t)row * 8;
        #pragma unroll
        for (int r = 0; r < 8; r++) out[r] = acc[r];
    }
}

// ---------------------------------------------------------------------------
// Kernel 2: SGEMM  C[m][n] = sum_k A[m][k] * W[n][k] + bias[n] (+ lora delta)
// 128x128x8 block tile, 8x8 per thread, 256 threads. M,N,K multiples of 128/8.
// FUSE_LORA: add LoRA delta for n<C (q) and n>=2C (v) using la [MTOT,8], lb [2C,4]
// ---------------------------------------------------------------------------
template <bool FUSE_LORA>
__global__ __launch_bounds__(256) void sgemm_wt_kernel(
    const float* __restrict__ A,      // [M, K]
    const float* __restrict__ W,      // [N, K]
    const float* __restrict__ bias,   // [N]
    const float* __restrict__ la,     // [M, 8] (lora a) or null
    const float* __restrict__ lb,     // [2C, 4] (lora B) or null
    float* __restrict__ C,
    int M, int N, int K)
{
    const int BM = 128, BN = 128, BK = 8, TM = 8, TN = 8;
    __shared__ float As[BK][BM];
    __shared__ float Bs[BK][BN];

    int tid  = threadIdx.x;
    int brow = blockIdx.y * BM;
    int bcol = blockIdx.x * BN;

    int trow = (tid >> 4) * TM;   // 16 thread-rows
    int tcol = (tid & 15) * TN;   // 16 thread-cols

    int lrow = tid >> 1;          // 0..127
    int lcol = (tid & 1) * 4;     // 0 or 4

    const float* Ab = A + (size_t)brow * K;
    const float* Wb = W + (size_t)bcol * K;

    float acc[TM][TN];
    #pragma unroll
    for (int i = 0; i < TM; i++)
        #pragma unroll
        for (int j = 0; j < TN; j++) acc[i][j] = 0.f;

    for (int k0 = 0; k0 < K; k0 += BK) {
        float4 a4 = *(const float4*)(Ab + (size_t)lrow * K + k0 + lcol);
        float4 b4 = *(const float4*)(Wb + (size_t)lrow * K + k0 + lcol);
        As[lcol + 0][lrow] = a4.x;  As[lcol + 1][lrow] = a4.y;
        As[lcol + 2][lrow] = a4.z;  As[lcol + 3][lrow] = a4.w;
        Bs[lcol + 0][lrow] = b4.x;  Bs[lcol + 1][lrow] = b4.y;
        Bs[lcol + 2][lrow] = b4.z;  Bs[lcol + 3][lrow] = b4.w;
        __syncthreads();

        #pragma unroll
        for (int k = 0; k < BK; k++) {
            float ar[TM], br[TN];
            *(float4*)&ar[0] = *(const float4*)&As[k][trow];
            *(float4*)&ar[4] = *(const float4*)&As[k][trow + 4];
            *(float4*)&br[0] = *(const float4*)&Bs[k][tcol];
            *(float4*)&br[4] = *(const float4*)&Bs[k][tcol + 4];
            #pragma unroll
            for (int i = 0; i < TM; i++)
                #pragma unroll
                for (int j = 0; j < TN; j++)
                    acc[i][j] += ar[i] * br[j];
        }
        __syncthreads();
    }

    // epilogue
    #pragma unroll
    for (int i = 0; i < TM; i++) {
        int m = brow + trow + i;
        float la0 = 0.f, la1 = 0.f, la2 = 0.f, la3 = 0.f;
        bool do_q = false, do_v = false;
        if (FUSE_LORA) {
            // per-block column region is uniform (bcol multiple of 128, C=1024)
            do_q = (bcol < C_);
            do_v = (bcol >= 2 * C_);
            if (do_q) {
                la0 = la[(size_t)m * 8 + 0]; la1 = la[(size_t)m * 8 + 1];
                la2 = la[(size_t)m * 8 + 2]; la3 = la[(size_t)m * 8 + 3];
            } else if (do_v) {
                la0 = la[(size_t)m * 8 + 4]; la1 = la[(size_t)m * 8 + 5];
                la2 = la[(size_t)m * 8 + 6]; la3 = la[(size_t)m * 8 + 7];
            }
        }
        #pragma unroll
        for (int j = 0; j < TN; j++) {
            int n = bcol + tcol + j;
            float v = acc[i][j] + bias[n];
            if (FUSE_LORA && (do_q || do_v)) {
                int o = do_q ? n : (C_ + (n - 2 * C_));   // row into lb [2C,4]
                const float* lbr = lb + (size_t)o * LORA_R;
                float d = la0 * lbr[0] + la1 * lbr[1] + la2 * lbr[2] + la3 * lbr[3];
                v += LORA_SCALE * d;
            }
            C[(size_t)m * N + n] = v;
        }
    }
}

// ---------------------------------------------------------------------------
// Kernel 3: flash attention, thread-per-query.
// qkv layout: [MTOT][3C]; q at col h*64, k at C + h*64, v at 2C + h*64.
// out: [MTOT][C], column h*64+d.
// ---------------------------------------------------------------------------
#define KT 32
__global__ __launch_bounds__(128) void attn_kernel(
    const float* __restrict__ qkv, float* __restrict__ out)
{
    int bh = blockIdx.y;                  // 0..B*H-1
    int b  = bh >> 4;
    int h  = bh & 15;
    int q  = blockIdx.x * 128 + threadIdx.x;   // < 2048 by grid

    const float scale = 0.125f;           // 64^-0.5

    __shared__ float Ks[KT][HD_];
    __shared__ float Vs[KT][HD_];

    // load q row, pre-scaled
    float qr[HD_];
    const float* qptr = qkv + ((size_t)(b * N_ + q) * QKV_COLS) + h * HD_;
    #pragma unroll
    for (int d4 = 0; d4 < 16; d4++) {
        float4 t = *(const float4*)(qptr + 4 * d4);
        qr[4 * d4 + 0] = t.x * scale; qr[4 * d4 + 1] = t.y * scale;
        qr[4 * d4 + 2] = t.z * scale; qr[4 * d4 + 3] = t.w * scale;
    }

    float o[HD_];
    #pragma unroll
    for (int d = 0; d < HD_; d++) o[d] = 0.f;
    float m = -1e30f, l = 0.f;

    for (int ks = 0; ks < N_; ks += KT) {
        __syncthreads();
        // cooperative K/V tile load: KT*16 float4 slots each
        for (int it = threadIdx.x; it < KT * 16; it += 128) {
            int j = it >> 4, d4 = it & 15;
            const float* kp = qkv + ((size_t)(b * N_ + ks + j) * QKV_COLS)
                              + C_ + h * HD_ + d4 * 4;
            *(float4*)&Ks[j][d4 * 4] = *(const float4*)kp;
            *(float4*)&Vs[j][d4 * 4] = *(const float4*)(kp + C_);
        }
        __syncthreads();

        float s[KT];
        float tmax = -1e30f;
        #pragma unroll
        for (int j = 0; j < KT; j++) {
            float acc = 0.f;
            #pragma unroll
            for (int d4 = 0; d4 < 16; d4++) {
                float4 kk = *(const float4*)&Ks[j][4 * d4];
                acc += qr[4 * d4 + 0] * kk.x + qr[4 * d4 + 1] * kk.y
                     + qr[4 * d4 + 2] * kk.z + qr[4 * d4 + 3] * kk.w;
            }
            s[j] = acc;
            tmax = fmaxf(tmax, acc);
        }

        float mnew = fmaxf(m, tmax);
        float corr = __expf(m - mnew);
        l *= corr;
        #pragma unroll
        for (int d = 0; d < HD_; d++) o[d] *= corr;
        m = mnew;

        #pragma unroll
        for (int j = 0; j < KT; j++) {
            float p = __expf(s[j] - m);
            l += p;
            #pragma unroll
            for (int d4 = 0; d4 < 16; d4++) {
                float4 vv = *(const float4*)&Vs[j][4 * d4];
                o[4 * d4 + 0] += p * vv.x; o[4 * d4 + 1] += p * vv.y;
                o[4 * d4 + 2] += p * vv.z; o[4 * d4 + 3] += p * vv.w;
            }
        }
    }

    float inv = 1.f / l;
    float* op = out + ((size_t)(b * N_ + q) * C_) + h * HD_;
    #pragma unroll
    for (int d4 = 0; d4 < 16; d4++) {
        float4 t;
        t.x = o[4 * d4 + 0] * inv; t.y = o[4 * d4 + 1] * inv;
        t.z = o[4 * d4 + 2] * inv; t.w = o[4 * d4 + 3] * inv;
        *(float4*)(op + 4 * d4) = t;
    }
}

// ---------------------------------------------------------------------------
// host launch
// ---------------------------------------------------------------------------
extern "C" void kernel_launch(void* const* d_in, const int* in_sizes, int n_in,
                              void* d_out, int out_size)
{
    const float* x      = (const float*)d_in[0];   // [2,2048,1024]
    const float* W_qkv  = (const float*)d_in[1];   // [3072,1024]
    const float* b_qkv  = (const float*)d_in[2];   // [3072]
    const float* lora_A = (const float*)d_in[3];   // [8,1024]
    const float* lora_B = (const float*)d_in[4];   // [2048,4]
    const float* W_proj = (const float*)d_in[5];   // [1024,1024]
    const float* b_proj = (const float*)d_in[6];   // [1024]
    // d_in[7] = idx (ignored; adapters identical)
    float* out = (float*)d_out;

    void* p;
    cudaGetSymbolAddress(&p, g_qkv);  float* qkv  = (float*)p;
    cudaGetSymbolAddress(&p, g_attn); float* attn = (float*)p;
    cudaGetSymbolAddress(&p, g_la);   float* la   = (float*)p;

    // 1. LoRA activations
    lora_a_kernel<<<MTOT / 8, 256>>>(x, lora_A, la);

    // 2. fused QKV GEMM + bias + LoRA delta
    {
        dim3 grid(QKV_COLS / 128, MTOT / 128);
        sgemm_wt_kernel<true><<<grid, 256>>>(x, W_qkv, b_qkv, la, lora_B,
                                             qkv, MTOT, QKV_COLS, C_);
    }

    // 3. attention
    {
        dim3 grid(N_ / 128, B_ * H_);
        attn_kernel<<<grid, 128>>>(qkv, attn);
    }

    // 4. output projection
    {
        dim3 grid(C_ / 128, MTOT / 128);
        sgemm_wt_kernel<false><<<grid, 256>>>(attn, W_proj, b_proj,
                                              nullptr, nullptr,
                                              out, MTOT, C_, C_);
    }
}

// round 2
// speedup vs baseline: 1.6643x; 1.6643x over previous
#include <cuda_runtime.h>
#include <cuda_bf16.h>
#include <cstdint>

// Problem constants (fixed shapes from the reference)
#define B_   2
#define N_   2048
#define C_   1024
#define H_   16
#define HD_  64
#define MTOT (B_ * N_)          // 4096
#define QKV_COLS (3 * C_)       // 3072
#define LORA_R 4
#define LORA_SCALE 0.25f

// ---------------------------------------------------------------------------
// Scratch (static device globals -> no allocation, graph-capturable)
// ---------------------------------------------------------------------------
__device__ float g_qkv[(size_t)MTOT * QKV_COLS];   // 50.3 MB
__device__ float g_attn[(size_t)MTOT * C_];        // 16.8 MB
__device__ float g_la[(size_t)MTOT * 8];           // 128 KB

// ---------------------------------------------------------------------------
// helpers: tf32 convert, packed f32x2 ops
// ---------------------------------------------------------------------------
__device__ __forceinline__ float to_tf32(float x) {
    uint32_t u;
    asm("cvt.rna.tf32.f32 %0, %1;" : "=r"(u) : "f"(x));
    return __uint_as_float(u);
}

__device__ __forceinline__ unsigned long long fma2(
    unsigned long long a, unsigned long long b, unsigned long long c) {
    unsigned long long d;
    asm("fma.rn.f32x2 %0, %1, %2, %3;" : "=l"(d) : "l"(a), "l"(b), "l"(c));
    return d;
}
__device__ __forceinline__ unsigned long long mul2(
    unsigned long long a, unsigned long long b) {
    unsigned long long d;
    asm("mul.rn.f32x2 %0, %1, %2;" : "=l"(d) : "l"(a), "l"(b));
    return d;
}
__device__ __forceinline__ unsigned long long pack2(float x, float y) {
    unsigned long long d;
    asm("mov.b64 %0, {%1, %2};" : "=l"(d) : "f"(x), "f"(y));
    return d;
}
__device__ __forceinline__ void unpack2(unsigned long long v, float& x, float& y) {
    asm("mov.b64 {%0, %1}, %2;" : "=f"(x), "=f"(y) : "l"(v));
}

// ---------------------------------------------------------------------------
// Kernel 1: lora activations  la[m][r] = sum_k x[m][k] * lora_A[r][k]
// ---------------------------------------------------------------------------
__global__ __launch_bounds__(256) void lora_a_kernel(
    const float* __restrict__ x,       // [MTOT, C]
    const float* __restrict__ la_w,    // [8, C]
    float* __restrict__ la)            // [MTOT, 8]
{
    int warp = threadIdx.x >> 5;
    int lane = threadIdx.x & 31;
    int row  = blockIdx.x * 8 + warp;
    if (row >= MTOT) return;
    const float* xr = x + (size_t)row * C_;
    float acc[8] = {0.f,0.f,0.f,0.f,0.f,0.f,0.f,0.f};
    for (int k = lane; k < C_; k += 32) {
        float xv = xr[k];
        #pragma unroll
        for (int r = 0; r < 8; r++) acc[r] += xv * la_w[r * C_ + k];
    }
    #pragma unroll
    for (int r = 0; r < 8; r++) {
        #pragma unroll
        for (int off = 16; off; off >>= 1)
            acc[r] += __shfl_xor_sync(0xffffffffu, acc[r], off);
    }
    if (lane == 0) {
        float* out = la + (size_t)row * 8;
        #pragma unroll
        for (int r = 0; r < 8; r++) out[r] = acc[r];
    }
}

// ---------------------------------------------------------------------------
// Kernel 2: tf32 tensor-core GEMM.
//   C[m][n] = sum_k A[m][k]*W[n][k] + bias[n]  (+ LoRA delta when FUSE_LORA)
// Block 128x128, BK=32, 256 threads = 8 warps as 2(m) x 4(n),
// warp tile 64(m) x 32(n), mma.sync m16n8k8 tf32.
// ---------------------------------------------------------------------------
#define SA 36   // smem row stride (32 + 4 pad): (4r+k)%32 bijective -> conflict-free
template <bool FUSE_LORA>
__global__ __launch_bounds__(256) void mma_gemm_kernel(
    const float* __restrict__ A,      // [M, K]
    const float* __restrict__ W,      // [N, K]
    const float* __restrict__ bias,   // [N]
    const float* __restrict__ la,     // [M, 8] or null
    const float* __restrict__ lb,     // [2C, 4] or null
    float* __restrict__ C,
    int M, int N, int K)
{
    __shared__ float As[128 * SA];
    __shared__ float Bs[128 * SA];

    const int tid  = threadIdx.x;
    const int warp = tid >> 5;
    const int lane = tid & 31;
    const int wm = warp & 1;          // 0..1
    const int wn = warp >> 1;         // 0..3
    const int brow = blockIdx.y * 128;
    const int bcol = blockIdx.x * 128;

    const float* Ag = A + (size_t)brow * K;
    const float* Wg = W + (size_t)bcol * K;

    // per-thread gmem load slots: 4 float4 per tile (128 rows x 32 cols)
    const int lrow = tid >> 3;              // 0..31 base row, +32 per slot
    const int lkq  = (tid & 7) * 4;         // 0,4,...28

    float acc[4][4][4];
    #pragma unroll
    for (int i = 0; i < 4; i++)
        #pragma unroll
        for (int j = 0; j < 4; j++)
            #pragma unroll
            for (int r = 0; r < 4; r++) acc[i][j][r] = 0.f;

    // prologue: load chunk 0 into registers
    float4 abuf[4], bbuf[4];
    #pragma unroll
    for (int s = 0; s < 4; s++) {
        int row = lrow + s * 32;
        abuf[s] = *(const float4*)(Ag + (size_t)row * K + lkq);
        bbuf[s] = *(const float4*)(Wg + (size_t)row * K + lkq);
    }

    const int nchunks = K / 32;
    for (int kc = 0; kc < nchunks; kc++) {
        // store regs -> smem with tf32 rounding
        #pragma unroll
        for (int s = 0; s < 4; s++) {
            int row = lrow + s * 32;
            float4 a4 = abuf[s], b4 = bbuf[s];
            a4.x = to_tf32(a4.x); a4.y = to_tf32(a4.y);
            a4.z = to_tf32(a4.z); a4.w = to_tf32(a4.w);
            b4.x = to_tf32(b4.x); b4.y = to_tf32(b4.y);
            b4.z = to_tf32(b4.z); b4.w = to_tf32(b4.w);
            *(float4*)(As + row * SA + lkq) = a4;
            *(float4*)(Bs + row * SA + lkq) = b4;
        }
        __syncthreads();

        // prefetch next chunk (overlaps with mma below)
        if (kc + 1 < nchunks) {
            int k0 = (kc + 1) * 32;
            #pragma unroll
            for (int s = 0; s < 4; s++) {
                int row = lrow + s * 32;
                abuf[s] = *(const float4*)(Ag + (size_t)row * K + k0 + lkq);
                bbuf[s] = *(const float4*)(Wg + (size_t)row * K + k0 + lkq);
            }
        }

        // compute: 4 k-steps of 8
        #pragma unroll
        for (int ks = 0; ks < 4; ks++) {
            const int kk = ks * 8 + (lane & 3);
            uint32_t afr[4][4], bfr[4][2];
            #pragma unroll
            for (int mi = 0; mi < 4; mi++) {
                int rb = wm * 64 + mi * 16 + (lane >> 2);
                afr[mi][0] = __float_as_uint(As[rb * SA + kk]);
                afr[mi][1] = __float_as_uint(As[(rb + 8) * SA + kk]);
                afr[mi][2] = __float_as_uint(As[rb * SA + kk + 4]);
                afr[mi][3] = __float_as_uint(As[(rb + 8) * SA + kk + 4]);
            }
            #pragma unroll
            for (int ni = 0; ni < 4; ni++) {
                int nb = wn * 32 + ni * 8 + (lane >> 2);
                bfr[ni][0] = __float_as_uint(Bs[nb * SA + kk]);
                bfr[ni][1] = __float_as_uint(Bs[nb * SA + kk + 4]);
            }
            #pragma unroll
            for (int mi = 0; mi < 4; mi++)
                #pragma unroll
                for (int ni = 0; ni < 4; ni++) {
                    asm volatile(
                        "mma.sync.aligned.m16n8k8.row.col.f32.tf32.tf32.f32 "
                        "{%0,%1,%2,%3}, {%4,%5,%6,%7}, {%8,%9}, {%0,%1,%2,%3};"
                        : "+f"(acc[mi][ni][0]), "+f"(acc[mi][ni][1]),
                          "+f"(acc[mi][ni][2]), "+f"(acc[mi][ni][3])
                        : "r"(afr[mi][0]), "r"(afr[mi][1]),
                          "r"(afr[mi][2]), "r"(afr[mi][3]),
                          "r"(bfr[ni][0]), "r"(bfr[ni][1]));
                }
        }
        __syncthreads();
    }

    // epilogue
    const int r4 = lane >> 2;
    const int c4 = lane & 3;
    bool do_q = false, do_v = false;
    if (FUSE_LORA) { do_q = (bcol < C_); do_v = (bcol >= 2 * C_); }

    #pragma unroll
    for (int mi = 0; mi < 4; mi++) {
        int m1 = brow + wm * 64 + mi * 16 + r4;     // rows m1 and m1+8
        float laA[4] = {0,0,0,0}, laB[4] = {0,0,0,0};
        if (FUSE_LORA && (do_q || do_v)) {
            int off = do_q ? 0 : 4;
            const float* l1 = la + (size_t)m1 * 8 + off;
            const float* l2 = la + (size_t)(m1 + 8) * 8 + off;
            #pragma unroll
            for (int r = 0; r < 4; r++) { laA[r] = l1[r]; laB[r] = l2[r]; }
        }
        #pragma unroll
        for (int ni = 0; ni < 4; ni++) {
            int n1 = bcol + wn * 32 + ni * 8 + 2 * c4;   // cols n1, n1+1
            float b0 = bias[n1], b1 = bias[n1 + 1];
            float d00 = 0.f, d01 = 0.f, d10 = 0.f, d11 = 0.f;
            if (FUSE_LORA && (do_q || do_v)) {
                int o0 = do_q ? n1 : (C_ + (n1 - 2 * C_));
                const float* lb0 = lb + (size_t)o0 * LORA_R;
                const float* lb1 = lb0 + LORA_R;
                #pragma unroll
                for (int r = 0; r < 4; r++) {
                    d00 += laA[r] * lb0[r];  d01 += laA[r] * lb1[r];
                    d10 += laB[r] * lb0[r];  d11 += laB[r] * lb1[r];
                }
                d00 *= LORA_SCALE; d01 *= LORA_SCALE;
                d10 *= LORA_SCALE; d11 *= LORA_SCALE;
            }
            float2 v0, v1;
            v0.x = acc[mi][ni][0] + b0 + d00;
            v0.y = acc[mi][ni][1] + b1 + d01;
            v1.x = acc[mi][ni][2] + b0 + d10;
            v1.y = acc[mi][ni][3] + b1 + d11;
            *(float2*)(C + (size_t)m1 * N + n1)       = v0;
            *(float2*)(C + (size_t)(m1 + 8) * N + n1) = v1;
        }
    }
}

// ---------------------------------------------------------------------------
// Kernel 3: flash attention, thread-per-query, packed f32x2 math.
// ---------------------------------------------------------------------------
#define KT 32
__global__ __launch_bounds__(128) void attn_kernel(
    const float* __restrict__ qkv, float* __restrict__ out)
{
    int bh = blockIdx.y;                  // 0..B*H-1
    int b  = bh >> 4;
    int h  = bh & 15;
    int q  = blockIdx.x * 128 + threadIdx.x;

    const float scale = 0.125f;           // 64^-0.5

    __shared__ float Ks[KT][HD_];
    __shared__ float Vs[KT][HD_];

    // load q row (pre-scaled), packed into 32 x f32x2
    unsigned long long q2[32];
    const float* qptr = qkv + ((size_t)(b * N_ + q) * QKV_COLS) + h * HD_;
    #pragma unroll
    for (int d4 = 0; d4 < 16; d4++) {
        float4 t = *(const float4*)(qptr + 4 * d4);
        q2[2 * d4 + 0] = pack2(t.x * scale, t.y * scale);
        q2[2 * d4 + 1] = pack2(t.z * scale, t.w * scale);
    }

    unsigned long long o2[32];
    #pragma unroll
    for (int d = 0; d < 32; d++) o2[d] = 0ull;
    float m = -1e30f, l = 0.f;

    for (int ks = 0; ks < N_; ks += KT) {
        __syncthreads();
        for (int it = threadIdx.x; it < KT * 16; it += 128) {
            int j = it >> 4, d4 = it & 15;
            const float* kp = qkv + ((size_t)(b * N_ + ks + j) * QKV_COLS)
                              + C_ + h * HD_ + d4 * 4;
            *(float4*)&Ks[j][d4 * 4] = *(const float4*)kp;
            *(float4*)&Vs[j][d4 * 4] = *(const float4*)(kp + C_);
        }
        __syncthreads();

        float s[KT];
        float tmax = -1e30f;
        #pragma unroll
        for (int j = 0; j < KT; j++) {
            unsigned long long acc2 = 0ull;
            #pragma unroll
            for (int d4 = 0; d4 < 16; d4++) {
                ulonglong2 kk = *(const ulonglong2*)&Ks[j][4 * d4];
                acc2 = fma2(q2[2 * d4 + 0], kk.x, acc2);
                acc2 = fma2(q2[2 * d4 + 1], kk.y, acc2);
            }
            float ax, ay;
            unpack2(acc2, ax, ay);
            s[j] = ax + ay;
            tmax = fmaxf(tmax, s[j]);
        }

        float mnew = fmaxf(m, tmax);
        float corr = __expf(m - mnew);
        l *= corr;
        unsigned long long corr2 = pack2(corr, corr);
        #pragma unroll
        for (int d = 0; d < 32; d++) o2[d] = mul2(o2[d], corr2);
        m = mnew;

        #pragma unroll
        for (int j = 0; j < KT; j++) {
            float p = __expf(s[j] - m);
            l += p;
            unsigned long long p2 = pack2(p, p);
            #pragma unroll
            for (int d4 = 0; d4 < 16; d4++) {
                ulonglong2 vv = *(const ulonglong2*)&Vs[j][4 * d4];
                o2[2 * d4 + 0] = fma2(p2, vv.x, o2[2 * d4 + 0]);
                o2[2 * d4 + 1] = fma2(p2, vv.y, o2[2 * d4 + 1]);
            }
        }
    }

    float inv = 1.f / l;
    float* op = out + ((size_t)(b * N_ + q) * C_) + h * HD_;
    #pragma unroll
    for (int d4 = 0; d4 < 16; d4++) {
        float x0, y0, x1, y1;
        unpack2(o2[2 * d4 + 0], x0, y0);
        unpack2(o2[2 * d4 + 1], x1, y1);
        float4 t;
        t.x = x0 * inv; t.y = y0 * inv; t.z = x1 * inv; t.w = y1 * inv;
        *(float4*)(op + 4 * d4) = t;
    }
}

// ---------------------------------------------------------------------------
// host launch
// ---------------------------------------------------------------------------
extern "C" void kernel_launch(void* const* d_in, const int* in_sizes, int n_in,
                              void* d_out, int out_size)
{
    const float* x      = (const float*)d_in[0];   // [2,2048,1024]
    const float* W_qkv  = (const float*)d_in[1];   // [3072,1024]
    const float* b_qkv  = (const float*)d_in[2];   // [3072]
    const float* lora_A = (const float*)d_in[3];   // [8,1024]
    const float* lora_B = (const float*)d_in[4];   // [2048,4]
    const float* W_proj = (const float*)d_in[5];   // [1024,1024]
    const float* b_proj = (const float*)d_in[6];   // [1024]
    float* out = (float*)d_out;

    void* p;
    cudaGetSymbolAddress(&p, g_qkv);  float* qkv  = (float*)p;
    cudaGetSymbolAddress(&p, g_attn); float* attn = (float*)p;
    cudaGetSymbolAddress(&p, g_la);   float* la   = (float*)p;

    // 1. LoRA activations
    lora_a_kernel<<<MTOT / 8, 256>>>(x, lora_A, la);

    // 2. fused QKV GEMM (tf32 mma) + bias + LoRA delta
    {
        dim3 grid(QKV_COLS / 128, MTOT / 128);
        mma_gemm_kernel<true><<<grid, 256>>>(x, W_qkv, b_qkv, la, lora_B,
                                             qkv, MTOT, QKV_COLS, C_);
    }

    // 3. attention (packed f32x2)
    {
        dim3 grid(N_ / 128, B_ * H_);
        attn_kernel<<<grid, 128>>>(qkv, attn);
    }

    // 4. output projection (tf32 mma)
    {
        dim3 grid(C_ / 128, MTOT / 128);
        mma_gemm_kernel<false><<<grid, 256>>>(attn, W_proj, b_proj,
                                              nullptr, nullptr,
                                              out, MTOT, C_, C_);
    }
}

// round 3
// speedup vs baseline: 4.9445x; 2.9709x over previous
#include <cuda_runtime.h>
#include <cuda_fp16.h>
#include <cstdint>

// Problem constants (fixed shapes from the reference)
#define B_   2
#define N_   2048
#define C_   1024
#define H_   16
#define HD_  64
#define MTOT 4096
#define QKV_COLS 3072
#define LORA_R 4
#define LORA_SCALE 0.25f

// ---------------------------------------------------------------------------
// Scratch (static device globals -> no allocation, graph-capturable)
// ---------------------------------------------------------------------------
__device__ __half g_qkv16[(size_t)MTOT * QKV_COLS];  // 25.2 MB
__device__ float  g_attn[(size_t)MTOT * C_];         // 16.8 MB
__device__ float  g_la[(size_t)MTOT * 8];            // 128 KB

// ---------------------------------------------------------------------------
// helpers
// ---------------------------------------------------------------------------
__device__ __forceinline__ float to_tf32(float x) {
    uint32_t u;
    asm("cvt.rna.tf32.f32 %0, %1;" : "=r"(u) : "f"(x));
    return __uint_as_float(u);
}
__device__ __forceinline__ float ex2(float x) {
    float y;
    asm("ex2.approx.ftz.f32 %0, %1;" : "=f"(y) : "f"(x));
    return y;
}
__device__ __forceinline__ uint32_t s2u(const void* p) {
    return (uint32_t)__cvta_generic_to_shared(p);
}
__device__ __forceinline__ void ldsm_x4(uint32_t* r, uint32_t addr) {
    asm volatile("ldmatrix.sync.aligned.m8n8.x4.shared.b16 {%0,%1,%2,%3}, [%4];"
                 : "=r"(r[0]), "=r"(r[1]), "=r"(r[2]), "=r"(r[3]) : "r"(addr));
}
__device__ __forceinline__ void ldsm_x4_t(uint32_t* r, uint32_t addr) {
    asm volatile("ldmatrix.sync.aligned.m8n8.x4.trans.shared.b16 {%0,%1,%2,%3}, [%4];"
                 : "=r"(r[0]), "=r"(r[1]), "=r"(r[2]), "=r"(r[3]) : "r"(addr));
}
__device__ __forceinline__ void mma_f16(float* c, const uint32_t* a, const uint32_t* b) {
    asm volatile("mma.sync.aligned.m16n8k16.row.col.f32.f16.f16.f32 "
                 "{%0,%1,%2,%3}, {%4,%5,%6,%7}, {%8,%9}, {%0,%1,%2,%3};"
                 : "+f"(c[0]), "+f"(c[1]), "+f"(c[2]), "+f"(c[3])
                 : "r"(a[0]), "r"(a[1]), "r"(a[2]), "r"(a[3]),
                   "r"(b[0]), "r"(b[1]));
}
__device__ __forceinline__ uint32_t h2pack(float x, float y) {
    __half2 t = __floats2half2_rn(x, y);
    return *(uint32_t*)&t;
}

// ---------------------------------------------------------------------------
// Kernel 1: lora activations  la[m][r] = sum_k x[m][k] * lora_A[r][k]
// ---------------------------------------------------------------------------
__global__ __launch_bounds__(256) void lora_a_kernel(
    const float* __restrict__ x, const float* __restrict__ la_w,
    float* __restrict__ la)
{
    int warp = threadIdx.x >> 5;
    int lane = threadIdx.x & 31;
    int row  = blockIdx.x * 8 + warp;
    if (row >= MTOT) return;
    const float* xr = x + (size_t)row * C_;
    float acc[8] = {0.f,0.f,0.f,0.f,0.f,0.f,0.f,0.f};
    for (int k = lane; k < C_; k += 32) {
        float xv = xr[k];
        #pragma unroll
        for (int r = 0; r < 8; r++) acc[r] += xv * la_w[r * C_ + k];
    }
    #pragma unroll
    for (int r = 0; r < 8; r++) {
        #pragma unroll
        for (int off = 16; off; off >>= 1)
            acc[r] += __shfl_xor_sync(0xffffffffu, acc[r], off);
    }
    if (lane == 0) {
        float* out = la + (size_t)row * 8;
        #pragma unroll
        for (int r = 0; r < 8; r++) out[r] = acc[r];
    }
}

// ---------------------------------------------------------------------------
// Kernel 2: tf32 tensor-core GEMM (128x128x32, 8 warps 2x4, m16n8k8)
// HALF_OUT: write __half output (for qkv); else fp32.
// ---------------------------------------------------------------------------
#define SA 36
template <bool FUSE_LORA, bool HALF_OUT>
__global__ __launch_bounds__(256) void mma_gemm_kernel(
    const float* __restrict__ A, const float* __restrict__ W,
    const float* __restrict__ bias,
    const float* __restrict__ la, const float* __restrict__ lb,
    void* __restrict__ Cout, int M, int N, int K)
{
    __shared__ float As[128 * SA];
    __shared__ float Bs[128 * SA];

    const int tid  = threadIdx.x;
    const int warp = tid >> 5;
    const int lane = tid & 31;
    const int wm = warp & 1;
    const int wn = warp >> 1;
    const int brow = blockIdx.y * 128;
    const int bcol = blockIdx.x * 128;

    const float* Ag = A + (size_t)brow * K;
    const float* Wg = W + (size_t)bcol * K;

    const int lrow = tid >> 3;
    const int lkq  = (tid & 7) * 4;

    float acc[4][4][4];
    #pragma unroll
    for (int i = 0; i < 4; i++)
        #pragma unroll
        for (int j = 0; j < 4; j++)
            #pragma unroll
            for (int r = 0; r < 4; r++) acc[i][j][r] = 0.f;

    float4 abuf[4], bbuf[4];
    #pragma unroll
    for (int s = 0; s < 4; s++) {
        int row = lrow + s * 32;
        abuf[s] = *(const float4*)(Ag + (size_t)row * K + lkq);
        bbuf[s] = *(const float4*)(Wg + (size_t)row * K + lkq);
    }

    const int nchunks = K / 32;
    for (int kc = 0; kc < nchunks; kc++) {
        #pragma unroll
        for (int s = 0; s < 4; s++) {
            int row = lrow + s * 32;
            float4 a4 = abuf[s], b4 = bbuf[s];
            a4.x = to_tf32(a4.x); a4.y = to_tf32(a4.y);
            a4.z = to_tf32(a4.z); a4.w = to_tf32(a4.w);
            b4.x = to_tf32(b4.x); b4.y = to_tf32(b4.y);
            b4.z = to_tf32(b4.z); b4.w = to_tf32(b4.w);
            *(float4*)(As + row * SA + lkq) = a4;
            *(float4*)(Bs + row * SA + lkq) = b4;
        }
        __syncthreads();

        if (kc + 1 < nchunks) {
            int k0 = (kc + 1) * 32;
            #pragma unroll
            for (int s = 0; s < 4; s++) {
                int row = lrow + s * 32;
                abuf[s] = *(const float4*)(Ag + (size_t)row * K + k0 + lkq);
                bbuf[s] = *(const float4*)(Wg + (size_t)row * K + k0 + lkq);
            }
        }

        #pragma unroll
        for (int ks = 0; ks < 4; ks++) {
            const int kk = ks * 8 + (lane & 3);
            uint32_t afr[4][4], bfr[4][2];
            #pragma unroll
            for (int mi = 0; mi < 4; mi++) {
                int rb = wm * 64 + mi * 16 + (lane >> 2);
                afr[mi][0] = __float_as_uint(As[rb * SA + kk]);
                afr[mi][1] = __float_as_uint(As[(rb + 8) * SA + kk]);
                afr[mi][2] = __float_as_uint(As[rb * SA + kk + 4]);
                afr[mi][3] = __float_as_uint(As[(rb + 8) * SA + kk + 4]);
            }
            #pragma unroll
            for (int ni = 0; ni < 4; ni++) {
                int nb = wn * 32 + ni * 8 + (lane >> 2);
                bfr[ni][0] = __float_as_uint(Bs[nb * SA + kk]);
                bfr[ni][1] = __float_as_uint(Bs[nb * SA + kk + 4]);
            }
            #pragma unroll
            for (int mi = 0; mi < 4; mi++)
                #pragma unroll
                for (int ni = 0; ni < 4; ni++) {
                    asm volatile(
                        "mma.sync.aligned.m16n8k8.row.col.f32.tf32.tf32.f32 "
                        "{%0,%1,%2,%3}, {%4,%5,%6,%7}, {%8,%9}, {%0,%1,%2,%3};"
                        : "+f"(acc[mi][ni][0]), "+f"(acc[mi][ni][1]),
                          "+f"(acc[mi][ni][2]), "+f"(acc[mi][ni][3])
                        : "r"(afr[mi][0]), "r"(afr[mi][1]),
                          "r"(afr[mi][2]), "r"(afr[mi][3]),
                          "r"(bfr[ni][0]), "r"(bfr[ni][1]));
                }
        }
        __syncthreads();
    }

    const int r4 = lane >> 2;
    const int c4 = lane & 3;
    bool do_q = false, do_v = false;
    if (FUSE_LORA) { do_q = (bcol < C_); do_v = (bcol >= 2 * C_); }

    #pragma unroll
    for (int mi = 0; mi < 4; mi++) {
        int m1 = brow + wm * 64 + mi * 16 + r4;
        float laA[4] = {0,0,0,0}, laB[4] = {0,0,0,0};
        if (FUSE_LORA && (do_q || do_v)) {
            int off = do_q ? 0 : 4;
            const float* l1 = la + (size_t)m1 * 8 + off;
            const float* l2 = la + (size_t)(m1 + 8) * 8 + off;
            #pragma unroll
            for (int r = 0; r < 4; r++) { laA[r] = l1[r]; laB[r] = l2[r]; }
        }
        #pragma unroll
        for (int ni = 0; ni < 4; ni++) {
            int n1 = bcol + wn * 32 + ni * 8 + 2 * c4;
            float b0 = bias[n1], b1 = bias[n1 + 1];
            float d00 = 0.f, d01 = 0.f, d10 = 0.f, d11 = 0.f;
            if (FUSE_LORA && (do_q || do_v)) {
                int o0 = do_q ? n1 : (C_ + (n1 - 2 * C_));
                const float* lb0 = lb + (size_t)o0 * LORA_R;
                const float* lb1 = lb0 + LORA_R;
                #pragma unroll
                for (int r = 0; r < 4; r++) {
                    d00 += laA[r] * lb0[r];  d01 += laA[r] * lb1[r];
                    d10 += laB[r] * lb0[r];  d11 += laB[r] * lb1[r];
                }
                d00 *= LORA_SCALE; d01 *= LORA_SCALE;
                d10 *= LORA_SCALE; d11 *= LORA_SCALE;
            }
            float v00 = acc[mi][ni][0] + b0 + d00;
            float v01 = acc[mi][ni][1] + b1 + d01;
            float v10 = acc[mi][ni][2] + b0 + d10;
            float v11 = acc[mi][ni][3] + b1 + d11;
            if (HALF_OUT) {
                __half* Ch = (__half*)Cout;
                *(__half2*)(Ch + (size_t)m1 * N + n1)       = __floats2half2_rn(v00, v01);
                *(__half2*)(Ch + (size_t)(m1 + 8) * N + n1) = __floats2half2_rn(v10, v11);
            } else {
                float* Cf = (float*)Cout;
                *(float2*)(Cf + (size_t)m1 * N + n1)       = make_float2(v00, v01);
                *(float2*)(Cf + (size_t)(m1 + 8) * N + n1) = make_float2(v10, v11);
            }
        }
    }
}

// ---------------------------------------------------------------------------
// Kernel 3: tensor-core flash attention.
// CTA: 128 queries x one (b,h). 4 warps, 32 query rows each (2 m-tiles of 16).
// Loop over 64-key tiles: S = Q K^T (mma fp16), online softmax, O += P V.
// ---------------------------------------------------------------------------
#define SKW 72   // smem row stride in halves: conflict-free ldmatrix phases
__global__ __launch_bounds__(128) void attn_mma_kernel(
    const __half* __restrict__ qkv, float* __restrict__ out)
{
    __shared__ __half Qs[128 * SKW];   // 18 KB
    __shared__ __half Ks[64 * SKW];    // 9 KB
    __shared__ __half Vs[64 * SKW];    // 9 KB

    const int bh = blockIdx.y, b = bh >> 4, h = bh & 15;
    const int q0 = blockIdx.x * 128;
    const int tid = threadIdx.x, warp = tid >> 5, lane = tid & 31;
    const int g = lane >> 3, ri = lane & 7;
    const float cexp = 0.18033688f;    // 0.125 * log2(e)

    // Q tile -> smem (fp16 copy)
    for (int it = tid; it < 128 * 8; it += 128) {
        int r = it >> 3, s = it & 7;
        *(uint4*)&Qs[r * SKW + s * 8] =
            *((const uint4*)(qkv + ((size_t)(b * N_ + q0 + r) * QKV_COLS) + h * HD_) + s);
    }
    __syncthreads();

    // Q fragments: [mt][kc][4], rows warp*32 + mt*16, k-chunks of 16
    uint32_t qf[2][4][4];
    {
        int rb = warp * 32;
        #pragma unroll
        for (int mt = 0; mt < 2; mt++)
            #pragma unroll
            for (int kc = 0; kc < 4; kc++) {
                int row = rb + mt * 16 + (g & 1) * 8 + ri;
                int col = kc * 16 + (g >> 1) * 8;
                ldsm_x4(qf[mt][kc], s2u(&Qs[row * SKW + col]));
            }
    }

    float of[2][8][4];
    #pragma unroll
    for (int mt = 0; mt < 2; mt++)
        #pragma unroll
        for (int dt = 0; dt < 8; dt++)
            #pragma unroll
            for (int r = 0; r < 4; r++) of[mt][dt][r] = 0.f;
    float mrow[2][2] = {{-1e30f, -1e30f}, {-1e30f, -1e30f}};
    float lrow[2][2] = {{0.f, 0.f}, {0.f, 0.f}};

    for (int kt = 0; kt < N_ / 64; kt++) {
        __syncthreads();
        for (int it = tid; it < 64 * 8; it += 128) {
            int j = it >> 3, s = it & 7;
            const __half* base = qkv + ((size_t)(b * N_ + kt * 64 + j) * QKV_COLS)
                                 + C_ + h * HD_;
            *(uint4*)&Ks[j * SKW + s * 8] = *((const uint4*)base + s);
            *(uint4*)&Vs[j * SKW + s * 8] = *((const uint4*)(base + C_) + s);
        }
        __syncthreads();

        // S = Q K^T : sc[mt][nt][4], nt = 8-key column tiles
        float sc[2][8][4];
        #pragma unroll
        for (int mt = 0; mt < 2; mt++)
            #pragma unroll
            for (int nt = 0; nt < 8; nt++)
                #pragma unroll
                for (int r = 0; r < 4; r++) sc[mt][nt][r] = 0.f;

        #pragma unroll
        for (int kc = 0; kc < 4; kc++) {
            uint32_t bf[8][2];
            #pragma unroll
            for (int np = 0; np < 4; np++) {
                uint32_t t[4];
                int row = np * 16 + (g >> 1) * 8 + ri;   // key rows
                int col = kc * 16 + (g & 1) * 8;         // dim cols
                ldsm_x4(t, s2u(&Ks[row * SKW + col]));
                bf[2 * np][0] = t[0];     bf[2 * np][1] = t[1];
                bf[2 * np + 1][0] = t[2]; bf[2 * np + 1][1] = t[3];
            }
            #pragma unroll
            for (int mt = 0; mt < 2; mt++)
                #pragma unroll
                for (int nt = 0; nt < 8; nt++)
                    mma_f16(sc[mt][nt], qf[mt][kc], bf[nt]);
        }

        // online softmax (raw-logit max; scale folded into exp2)
        #pragma unroll
        for (int mt = 0; mt < 2; mt++)
            #pragma unroll
            for (int sub = 0; sub < 2; sub++) {
                float tm = -1e30f;
                #pragma unroll
                for (int nt = 0; nt < 8; nt++)
                    tm = fmaxf(tm, fmaxf(sc[mt][nt][2 * sub], sc[mt][nt][2 * sub + 1]));
                tm = fmaxf(tm, __shfl_xor_sync(0xffffffffu, tm, 1));
                tm = fmaxf(tm, __shfl_xor_sync(0xffffffffu, tm, 2));
                float mnew = fmaxf(mrow[mt][sub], tm);
                float corr = ex2((mrow[mt][sub] - mnew) * cexp);
                mrow[mt][sub] = mnew;
                lrow[mt][sub] *= corr;
                #pragma unroll
                for (int dt = 0; dt < 8; dt++) {
                    of[mt][dt][2 * sub]     *= corr;
                    of[mt][dt][2 * sub + 1] *= corr;
                }
                float lp = 0.f;
                #pragma unroll
                for (int nt = 0; nt < 8; nt++) {
                    float p0 = ex2((sc[mt][nt][2 * sub]     - mnew) * cexp);
                    float p1 = ex2((sc[mt][nt][2 * sub + 1] - mnew) * cexp);
                    sc[mt][nt][2 * sub] = p0; sc[mt][nt][2 * sub + 1] = p1;
                    lp += p0 + p1;
                }
                lrow[mt][sub] += lp;
            }

        // O += P V
        #pragma unroll
        for (int kc = 0; kc < 4; kc++) {
            uint32_t pa[2][4];
            #pragma unroll
            for (int mt = 0; mt < 2; mt++) {
                pa[mt][0] = h2pack(sc[mt][2 * kc][0],     sc[mt][2 * kc][1]);
                pa[mt][1] = h2pack(sc[mt][2 * kc][2],     sc[mt][2 * kc][3]);
                pa[mt][2] = h2pack(sc[mt][2 * kc + 1][0], sc[mt][2 * kc + 1][1]);
                pa[mt][3] = h2pack(sc[mt][2 * kc + 1][2], sc[mt][2 * kc + 1][3]);
            }
            uint32_t vb[8][2];
            #pragma unroll
            for (int dp = 0; dp < 4; dp++) {
                uint32_t t[4];
                int row = kc * 16 + (g & 1) * 8 + ri;    // key rows
                int col = dp * 16 + (g >> 1) * 8;        // dim cols
                ldsm_x4_t(t, s2u(&Vs[row * SKW + col]));
                vb[2 * dp][0] = t[0];     vb[2 * dp][1] = t[1];
                vb[2 * dp + 1][0] = t[2]; vb[2 * dp + 1][1] = t[3];
            }
            #pragma unroll
            for (int mt = 0; mt < 2; mt++)
                #pragma unroll
                for (int dt = 0; dt < 8; dt++)
                    mma_f16(of[mt][dt], pa[mt], vb[dt]);
        }
    }

    // epilogue: normalize by row sum, write fp32
    #pragma unroll
    for (int mt = 0; mt < 2; mt++)
        #pragma unroll
        for (int sub = 0; sub < 2; sub++) {
            float l = lrow[mt][sub];
            l += __shfl_xor_sync(0xffffffffu, l, 1);
            l += __shfl_xor_sync(0xffffffffu, l, 2);
            float inv = 1.f / l;
            int r = q0 + warp * 32 + mt * 16 + (lane >> 2) + sub * 8;
            float* op = out + ((size_t)(b * N_ + r) * C_) + h * HD_ + 2 * (lane & 3);
            #pragma unroll
            for (int dt = 0; dt < 8; dt++) {
                float2 v = make_float2(of[mt][dt][2 * sub] * inv,
                                       of[mt][dt][2 * sub + 1] * inv);
                *(float2*)(op + dt * 8) = v;
            }
        }
}

// ---------------------------------------------------------------------------
// host launch
// ---------------------------------------------------------------------------
extern "C" void kernel_launch(void* const* d_in, const int* in_sizes, int n_in,
                              void* d_out, int out_size)
{
    const float* x      = (const float*)d_in[0];
    const float* W_qkv  = (const float*)d_in[1];
    const float* b_qkv  = (const float*)d_in[2];
    const float* lora_A = (const float*)d_in[3];
    const float* lora_B = (const float*)d_in[4];
    const float* W_proj = (const float*)d_in[5];
    const float* b_proj = (const float*)d_in[6];
    float* out = (float*)d_out;

    void* p;
    cudaGetSymbolAddress(&p, g_qkv16); __half* qkv16 = (__half*)p;
    cudaGetSymbolAddress(&p, g_attn);  float*  attn  = (float*)p;
    cudaGetSymbolAddress(&p, g_la);    float*  la    = (float*)p;

    // 1. LoRA activations
    lora_a_kernel<<<MTOT / 8, 256>>>(x, lora_A, la);

    // 2. fused QKV GEMM (tf32 mma) + bias + LoRA delta -> fp16
    {
        dim3 grid(QKV_COLS / 128, MTOT / 128);
        mma_gemm_kernel<true, true><<<grid, 256>>>(x, W_qkv, b_qkv, la, lora_B,
                                                   qkv16, MTOT, QKV_COLS, C_);
    }

    // 3. flash attention (fp16 mma, fp32 accum)
    {
        dim3 grid(N_ / 128, B_ * H_);
        attn_mma_kernel<<<grid, 128>>>(qkv16, attn);
    }

    // 4. output projection (tf32 mma, fp32 out)
    {
        dim3 grid(C_ / 128, MTOT / 128);
        mma_gemm_kernel<false, false><<<grid, 256>>>(attn, W_proj, b_proj,
                                                     nullptr, nullptr,
                                                     out, MTOT, C_, C_);
    }
}

// round 4
// speedup vs baseline: 6.7703x; 1.3693x over previous
#include <cuda_runtime.h>
#include <cuda_fp16.h>
#include <cstdint>

// Problem constants (fixed shapes from the reference)
#define B_   2
#define N_   2048
#define C_   1024
#define H_   16
#define HD_  64
#define MTOT 4096
#define QKV_COLS 3072
#define LORA_R 4
#define LORA_SCALE 0.25f

// ---------------------------------------------------------------------------
// Scratch (static device globals -> no allocation, graph-capturable)
// ---------------------------------------------------------------------------
__device__ __half g_qkv16[(size_t)MTOT * QKV_COLS];   // 24 MB
__device__ __half g_attn16[(size_t)MTOT * C_];        // 8 MB
__device__ __half g_x16[(size_t)MTOT * C_];           // 8 MB
__device__ __half g_wqkv16[(size_t)QKV_COLS * C_];    // 6 MB
__device__ __half g_wproj16[(size_t)C_ * C_];         // 2 MB
__device__ float  g_la[(size_t)MTOT * 8];             // 128 KB

// ---------------------------------------------------------------------------
// helpers
// ---------------------------------------------------------------------------
__device__ __forceinline__ float ex2(float x) {
    float y;
    asm("ex2.approx.ftz.f32 %0, %1;" : "=f"(y) : "f"(x));
    return y;
}
__device__ __forceinline__ uint32_t s2u(const void* p) {
    return (uint32_t)__cvta_generic_to_shared(p);
}
__device__ __forceinline__ uint32_t sw128(uint32_t byteoff) {
    return byteoff ^ ((byteoff >> 3) & 0x70);
}
__device__ __forceinline__ void ldsm_x4(uint32_t* r, uint32_t addr) {
    asm volatile("ldmatrix.sync.aligned.m8n8.x4.shared.b16 {%0,%1,%2,%3}, [%4];"
                 : "=r"(r[0]), "=r"(r[1]), "=r"(r[2]), "=r"(r[3]) : "r"(addr));
}
__device__ __forceinline__ void ldsm_x4_t(uint32_t* r, uint32_t addr) {
    asm volatile("ldmatrix.sync.aligned.m8n8.x4.trans.shared.b16 {%0,%1,%2,%3}, [%4];"
                 : "=r"(r[0]), "=r"(r[1]), "=r"(r[2]), "=r"(r[3]) : "r"(addr));
}
__device__ __forceinline__ void mma_f16(float* c, const uint32_t* a, const uint32_t* b) {
    asm volatile("mma.sync.aligned.m16n8k16.row.col.f32.f16.f16.f32 "
                 "{%0,%1,%2,%3}, {%4,%5,%6,%7}, {%8,%9}, {%0,%1,%2,%3};"
                 : "+f"(c[0]), "+f"(c[1]), "+f"(c[2]), "+f"(c[3])
                 : "r"(a[0]), "r"(a[1]), "r"(a[2]), "r"(a[3]),
                   "r"(b[0]), "r"(b[1]));
}
__device__ __forceinline__ uint32_t h2pack(float x, float y) {
    __half2 t = __floats2half2_rn(x, y);
    return *(uint32_t*)&t;
}
__device__ __forceinline__ void cp_async16(uint32_t saddr, const void* gaddr) {
    asm volatile("cp.async.cg.shared.global [%0], [%1], 16;"
                 :: "r"(saddr), "l"(gaddr));
}
__device__ __forceinline__ void cp_commit() {
    asm volatile("cp.async.commit_group;");
}
template<int NW> __device__ __forceinline__ void cp_wait() {
    asm volatile("cp.async.wait_group %0;" :: "n"(NW));
}

// ---------------------------------------------------------------------------
// Kernel 0: fp32 -> fp16 convert (vectorized)
// ---------------------------------------------------------------------------
__global__ __launch_bounds__(256) void f2h_kernel(
    const float* __restrict__ in, __half* __restrict__ out, int n4)
{
    int i = blockIdx.x * 256 + threadIdx.x;
    if (i >= n4) return;
    float4 v = *(const float4*)(in + 4 * (size_t)i);
    __half2 h0 = __floats2half2_rn(v.x, v.y);
    __half2 h1 = __floats2half2_rn(v.z, v.w);
    uint2 o; o.x = *(uint32_t*)&h0; o.y = *(uint32_t*)&h1;
    *(uint2*)(out + 4 * (size_t)i) = o;
}

// ---------------------------------------------------------------------------
// Kernel 1: lora activations  la[m][r] = sum_k x[m][k] * lora_A[r][k]
// ---------------------------------------------------------------------------
__global__ __launch_bounds__(256) void lora_a_kernel(
    const float* __restrict__ x, const float* __restrict__ la_w,
    float* __restrict__ la)
{
    int warp = threadIdx.x >> 5;
    int lane = threadIdx.x & 31;
    int row  = blockIdx.x * 8 + warp;
    if (row >= MTOT) return;
    const float* xr = x + (size_t)row * C_;
    float acc[8] = {0.f,0.f,0.f,0.f,0.f,0.f,0.f,0.f};
    for (int k = lane; k < C_; k += 32) {
        float xv = xr[k];
        #pragma unroll
        for (int r = 0; r < 8; r++) acc[r] += xv * la_w[r * C_ + k];
    }
    #pragma unroll
    for (int r = 0; r < 8; r++) {
        #pragma unroll
        for (int off = 16; off; off >>= 1)
            acc[r] += __shfl_xor_sync(0xffffffffu, acc[r], off);
    }
    if (lane == 0) {
        float* out = la + (size_t)row * 8;
        #pragma unroll
        for (int r = 0; r < 8; r++) out[r] = acc[r];
    }
}

// ---------------------------------------------------------------------------
// Kernel 2: fp16 tensor-core GEMM (fp32 accum).
//   C[m][n] = sum_k A[m][k]*W[n][k] + bias[n]  (+ LoRA delta)
// Block 128x128, BK=64 halves, 2-stage cp.async pipeline, SW128 smem,
// 8 warps (2m x 4n), warp tile 64x32, mma m16n8k16 via ldmatrix.
// ---------------------------------------------------------------------------
#define BKH 64
#define STAGE_BYTES (128 * BKH * 2)   // 16 KB per operand per stage
template <bool FUSE_LORA, bool HALF_OUT>
__global__ __launch_bounds__(256) void hgemm_kernel(
    const __half* __restrict__ A, const __half* __restrict__ W,
    const float* __restrict__ bias,
    const float* __restrict__ la, const float* __restrict__ lb,
    void* __restrict__ Cout, int M, int N, int K)
{
    extern __shared__ __half smem[];
    const uint32_t sA = s2u(smem);                       // 2 stages A
    const uint32_t sB = sA + 2 * STAGE_BYTES;            // 2 stages B

    const int tid  = threadIdx.x;
    const int warp = tid >> 5;
    const int lane = tid & 31;
    const int wm = warp & 1;
    const int wn = warp >> 1;
    const int brow = blockIdx.y * 128;
    const int bcol = blockIdx.x * 128;
    const int g = lane >> 3, ri = lane & 7;

    const __half* Ag = A + (size_t)brow * K;
    const __half* Wg = W + (size_t)bcol * K;

    const int lr = tid >> 3;       // row base 0..31 (+32*s)
    const int lc = tid & 7;        // 16B chunk in row

    float acc[4][4][4];
    #pragma unroll
    for (int i = 0; i < 4; i++)
        #pragma unroll
        for (int j = 0; j < 4; j++)
            #pragma unroll
            for (int r = 0; r < 4; r++) acc[i][j][r] = 0.f;

    auto load_stage = [&](int st, int k0) {
        uint32_t bA = sA + st * STAGE_BYTES;
        uint32_t bB = sB + st * STAGE_BYTES;
        #pragma unroll
        for (int s = 0; s < 4; s++) {
            int row = lr + s * 32;
            uint32_t off = sw128(row * 128 + lc * 16);
            cp_async16(bA + off, Ag + (size_t)row * K + k0 + lc * 8);
            cp_async16(bB + off, Wg + (size_t)row * K + k0 + lc * 8);
        }
        cp_commit();
    };

    load_stage(0, 0);
    const int niter = K / BKH;
    for (int it = 0; it < niter; it++) {
        if (it + 1 < niter) { load_stage((it + 1) & 1, (it + 1) * BKH); cp_wait<1>(); }
        else                 cp_wait<0>();
        __syncthreads();

        uint32_t bA = sA + (it & 1) * STAGE_BYTES;
        uint32_t bB = sB + (it & 1) * STAGE_BYTES;

        #pragma unroll
        for (int kc = 0; kc < 4; kc++) {
            uint32_t af[4][4];
            #pragma unroll
            for (int mi = 0; mi < 4; mi++) {
                int row  = wm * 64 + mi * 16 + (g & 1) * 8 + ri;
                int colb = kc * 32 + (g >> 1) * 16;
                ldsm_x4(af[mi], bA + sw128(row * 128 + colb));
            }
            uint32_t bf[4][2];
            #pragma unroll
            for (int np = 0; np < 2; np++) {
                uint32_t t[4];
                int row  = wn * 32 + np * 16 + (g >> 1) * 8 + ri;
                int colb = kc * 32 + (g & 1) * 16;
                ldsm_x4(t, bB + sw128(row * 128 + colb));
                bf[2 * np][0] = t[0];     bf[2 * np][1] = t[1];
                bf[2 * np + 1][0] = t[2]; bf[2 * np + 1][1] = t[3];
            }
            #pragma unroll
            for (int mi = 0; mi < 4; mi++)
                #pragma unroll
                for (int ni = 0; ni < 4; ni++)
                    mma_f16(acc[mi][ni], af[mi], bf[ni]);
        }
        __syncthreads();
    }

    // epilogue
    const int r4 = lane >> 2;
    const int c4 = lane & 3;
    bool do_q = false, do_v = false;
    if (FUSE_LORA) { do_q = (bcol < C_); do_v = (bcol >= 2 * C_); }

    #pragma unroll
    for (int mi = 0; mi < 4; mi++) {
        int m1 = brow + wm * 64 + mi * 16 + r4;
        float laA[4] = {0,0,0,0}, laB[4] = {0,0,0,0};
        if (FUSE_LORA && (do_q || do_v)) {
            int off = do_q ? 0 : 4;
            const float* l1 = la + (size_t)m1 * 8 + off;
            const float* l2 = la + (size_t)(m1 + 8) * 8 + off;
            #pragma unroll
            for (int r = 0; r < 4; r++) { laA[r] = l1[r]; laB[r] = l2[r]; }
        }
        #pragma unroll
        for (int ni = 0; ni < 4; ni++) {
            int n1 = bcol + wn * 32 + ni * 8 + 2 * c4;
            float b0 = bias[n1], b1 = bias[n1 + 1];
            float d00 = 0.f, d01 = 0.f, d10 = 0.f, d11 = 0.f;
            if (FUSE_LORA && (do_q || do_v)) {
                int o0 = do_q ? n1 : (C_ + (n1 - 2 * C_));
                const float* lb0 = lb + (size_t)o0 * LORA_R;
                const float* lb1 = lb0 + LORA_R;
                #pragma unroll
                for (int r = 0; r < 4; r++) {
                    d00 += laA[r] * lb0[r];  d01 += laA[r] * lb1[r];
                    d10 += laB[r] * lb0[r];  d11 += laB[r] * lb1[r];
                }
                d00 *= LORA_SCALE; d01 *= LORA_SCALE;
                d10 *= LORA_SCALE; d11 *= LORA_SCALE;
            }
            float v00 = acc[mi][ni][0] + b0 + d00;
            float v01 = acc[mi][ni][1] + b1 + d01;
            float v10 = acc[mi][ni][2] + b0 + d10;
            float v11 = acc[mi][ni][3] + b1 + d11;
            if (HALF_OUT) {
                __half* Ch = (__half*)Cout;
                *(__half2*)(Ch + (size_t)m1 * N + n1)       = __floats2half2_rn(v00, v01);
                *(__half2*)(Ch + (size_t)(m1 + 8) * N + n1) = __floats2half2_rn(v10, v11);
            } else {
                float* Cf = (float*)Cout;
                *(float2*)(Cf + (size_t)m1 * N + n1)       = make_float2(v00, v01);
                *(float2*)(Cf + (size_t)(m1 + 8) * N + n1) = make_float2(v10, v11);
            }
        }
    }
}

// ---------------------------------------------------------------------------
// Kernel 3: tensor-core flash attention (fp16 in, fp32 accum, fp16 out).
// ---------------------------------------------------------------------------
#define SKW 72
__global__ __launch_bounds__(128) void attn_mma_kernel(
    const __half* __restrict__ qkv, __half* __restrict__ out)
{
    __shared__ __half Qs[128 * SKW];
    __shared__ __half Ks[64 * SKW];
    __shared__ __half Vs[64 * SKW];

    const int bh = blockIdx.y, b = bh >> 4, h = bh & 15;
    const int q0 = blockIdx.x * 128;
    const int tid = threadIdx.x, warp = tid >> 5, lane = tid & 31;
    const int g = lane >> 3, ri = lane & 7;
    const float cexp = 0.18033688f;    // 0.125 * log2(e)

    for (int it = tid; it < 128 * 8; it += 128) {
        int r = it >> 3, s = it & 7;
        *(uint4*)&Qs[r * SKW + s * 8] =
            *((const uint4*)(qkv + ((size_t)(b * N_ + q0 + r) * QKV_COLS) + h * HD_) + s);
    }
    __syncthreads();

    uint32_t qf[2][4][4];
    {
        int rb = warp * 32;
        #pragma unroll
        for (int mt = 0; mt < 2; mt++)
            #pragma unroll
            for (int kc = 0; kc < 4; kc++) {
                int row = rb + mt * 16 + (g & 1) * 8 + ri;
                int col = kc * 16 + (g >> 1) * 8;
                ldsm_x4(qf[mt][kc], s2u(&Qs[row * SKW + col]));
            }
    }

    float of[2][8][4];
    #pragma unroll
    for (int mt = 0; mt < 2; mt++)
        #pragma unroll
        for (int dt = 0; dt < 8; dt++)
            #pragma unroll
            for (int r = 0; r < 4; r++) of[mt][dt][r] = 0.f;
    float mrow[2][2] = {{-1e30f, -1e30f}, {-1e30f, -1e30f}};
    float lrow[2][2] = {{0.f, 0.f}, {0.f, 0.f}};

    for (int kt = 0; kt < N_ / 64; kt++) {
        __syncthreads();
        for (int it = tid; it < 64 * 8; it += 128) {
            int j = it >> 3, s = it & 7;
            const __half* base = qkv + ((size_t)(b * N_ + kt * 64 + j) * QKV_COLS)
                                 + C_ + h * HD_;
            *(uint4*)&Ks[j * SKW + s * 8] = *((const uint4*)base + s);
            *(uint4*)&Vs[j * SKW + s * 8] = *((const uint4*)(base + C_) + s);
        }
        __syncthreads();

        float sc[2][8][4];
        #pragma unroll
        for (int mt = 0; mt < 2; mt++)
            #pragma unroll
            for (int nt = 0; nt < 8; nt++)
                #pragma unroll
                for (int r = 0; r < 4; r++) sc[mt][nt][r] = 0.f;

        #pragma unroll
        for (int kc = 0; kc < 4; kc++) {
            uint32_t bf[8][2];
            #pragma unroll
            for (int np = 0; np < 4; np++) {
                uint32_t t[4];
                int row = np * 16 + (g >> 1) * 8 + ri;
                int col = kc * 16 + (g & 1) * 8;
                ldsm_x4(t, s2u(&Ks[row * SKW + col]));
                bf[2 * np][0] = t[0];     bf[2 * np][1] = t[1];
                bf[2 * np + 1][0] = t[2]; bf[2 * np + 1][1] = t[3];
            }
            #pragma unroll
            for (int mt = 0; mt < 2; mt++)
                #pragma unroll
                for (int nt = 0; nt < 8; nt++)
                    mma_f16(sc[mt][nt], qf[mt][kc], bf[nt]);
        }

        #pragma unroll
        for (int mt = 0; mt < 2; mt++)
            #pragma unroll
            for (int sub = 0; sub < 2; sub++) {
                float tm = -1e30f;
                #pragma unroll
                for (int nt = 0; nt < 8; nt++)
                    tm = fmaxf(tm, fmaxf(sc[mt][nt][2 * sub], sc[mt][nt][2 * sub + 1]));
                tm = fmaxf(tm, __shfl_xor_sync(0xffffffffu, tm, 1));
                tm = fmaxf(tm, __shfl_xor_sync(0xffffffffu, tm, 2));
                float mnew = fmaxf(mrow[mt][sub], tm);
                float corr = ex2((mrow[mt][sub] - mnew) * cexp);
                mrow[mt][sub] = mnew;
                lrow[mt][sub] *= corr;
                #pragma unroll
                for (int dt = 0; dt < 8; dt++) {
                    of[mt][dt][2 * sub]     *= corr;
                    of[mt][dt][2 * sub + 1] *= corr;
                }
                float lp = 0.f;
                #pragma unroll
                for (int nt = 0; nt < 8; nt++) {
                    float p0 = ex2((sc[mt][nt][2 * sub]     - mnew) * cexp);
                    float p1 = ex2((sc[mt][nt][2 * sub + 1] - mnew) * cexp);
                    sc[mt][nt][2 * sub] = p0; sc[mt][nt][2 * sub + 1] = p1;
                    lp += p0 + p1;
                }
                lrow[mt][sub] += lp;
            }

        #pragma unroll
        for (int kc = 0; kc < 4; kc++) {
            uint32_t pa[2][4];
            #pragma unroll
            for (int mt = 0; mt < 2; mt++) {
                pa[mt][0] = h2pack(sc[mt][2 * kc][0],     sc[mt][2 * kc][1]);
                pa[mt][1] = h2pack(sc[mt][2 * kc][2],     sc[mt][2 * kc][3]);
                pa[mt][2] = h2pack(sc[mt][2 * kc + 1][0], sc[mt][2 * kc + 1][1]);
                pa[mt][3] = h2pack(sc[mt][2 * kc + 1][2], sc[mt][2 * kc + 1][3]);
            }
            uint32_t vb[8][2];
            #pragma unroll
            for (int dp = 0; dp < 4; dp++) {
                uint32_t t[4];
                int row = kc * 16 + (g & 1) * 8 + ri;
                int col = dp * 16 + (g >> 1) * 8;
                ldsm_x4_t(t, s2u(&Vs[row * SKW + col]));
                vb[2 * dp][0] = t[0];     vb[2 * dp][1] = t[1];
                vb[2 * dp + 1][0] = t[2]; vb[2 * dp + 1][1] = t[3];
            }
            #pragma unroll
            for (int mt = 0; mt < 2; mt++)
                #pragma unroll
                for (int dt = 0; dt < 8; dt++)
                    mma_f16(of[mt][dt], pa[mt], vb[dt]);
        }
    }

    #pragma unroll
    for (int mt = 0; mt < 2; mt++)
        #pragma unroll
        for (int sub = 0; sub < 2; sub++) {
            float l = lrow[mt][sub];
            l += __shfl_xor_sync(0xffffffffu, l, 1);
            l += __shfl_xor_sync(0xffffffffu, l, 2);
            float inv = 1.f / l;
            int r = q0 + warp * 32 + mt * 16 + (lane >> 2) + sub * 8;
            __half* op = out + ((size_t)(b * N_ + r) * C_) + h * HD_ + 2 * (lane & 3);
            #pragma unroll
            for (int dt = 0; dt < 8; dt++) {
                *(__half2*)(op + dt * 8) =
                    __floats2half2_rn(of[mt][dt][2 * sub] * inv,
                                      of[mt][dt][2 * sub + 1] * inv);
            }
        }
}

// ---------------------------------------------------------------------------
// host launch
// ---------------------------------------------------------------------------
extern "C" void kernel_launch(void* const* d_in, const int* in_sizes, int n_in,
                              void* d_out, int out_size)
{
    const float* x      = (const float*)d_in[0];
    const float* W_qkv  = (const float*)d_in[1];
    const float* b_qkv  = (const float*)d_in[2];
    const float* lora_A = (const float*)d_in[3];
    const float* lora_B = (const float*)d_in[4];
    const float* W_proj = (const float*)d_in[5];
    const float* b_proj = (const float*)d_in[6];
    float* out = (float*)d_out;

    void* p;
    cudaGetSymbolAddress(&p, g_qkv16);   __half* qkv16   = (__half*)p;
    cudaGetSymbolAddress(&p, g_attn16);  __half* attn16  = (__half*)p;
    cudaGetSymbolAddress(&p, g_x16);     __half* x16     = (__half*)p;
    cudaGetSymbolAddress(&p, g_wqkv16);  __half* wqkv16  = (__half*)p;
    cudaGetSymbolAddress(&p, g_wproj16); __half* wproj16 = (__half*)p;
    cudaGetSymbolAddress(&p, g_la);      float*  la      = (float*)p;

    const int SMEM = 4 * STAGE_BYTES;   // 64 KB
    cudaFuncSetAttribute(hgemm_kernel<true,  true>,
                         cudaFuncAttributeMaxDynamicSharedMemorySize, SMEM);
    cudaFuncSetAttribute(hgemm_kernel<false, false>,
                         cudaFuncAttributeMaxDynamicSharedMemorySize, SMEM);

    // 0. converts
    f2h_kernel<<<(MTOT * C_ / 4 + 255) / 256, 256>>>(x, x16, MTOT * C_ / 4);
    f2h_kernel<<<(QKV_COLS * C_ / 4 + 255) / 256, 256>>>(W_qkv, wqkv16, QKV_COLS * C_ / 4);
    f2h_kernel<<<(C_ * C_ / 4 + 255) / 256, 256>>>(W_proj, wproj16, C_ * C_ / 4);

    // 1. LoRA activations
    lora_a_kernel<<<MTOT / 8, 256>>>(x, lora_A, la);

    // 2. fused QKV GEMM (fp16 mma) + bias + LoRA delta -> fp16
    {
        dim3 grid(QKV_COLS / 128, MTOT / 128);
        hgemm_kernel<true, true><<<grid, 256, SMEM>>>(
            x16, wqkv16, b_qkv, la, lora_B, qkv16, MTOT, QKV_COLS, C_);
    }

    // 3. flash attention -> fp16
    {
        dim3 grid(N_ / 128, B_ * H_);
        attn_mma_kernel<<<grid, 128>>>(qkv16, attn16);
    }

    // 4. output projection (fp16 mma, fp32 out)
    {
        dim3 grid(C_ / 128, MTOT / 128);
        hgemm_kernel<false, false><<<grid, 256, SMEM>>>(
            attn16, wproj16, b_proj, nullptr, nullptr, out, MTOT, C_, C_);
    }
}

// round 5
// speedup vs baseline: 8.3562x; 1.2342x over previous
#include <cuda_runtime.h>
#include <cuda_fp16.h>
#include <cstdint>

// Problem constants (fixed shapes from the reference)
#define B_   2
#define N_   2048
#define C_   1024
#define H_   16
#define HD_  64
#define MTOT 4096
#define QKV_COLS 3072
#define LORA_R 4
#define LORA_SCALE 0.25f

// ---------------------------------------------------------------------------
// Scratch (static device globals -> no allocation, graph-capturable)
// ---------------------------------------------------------------------------
__device__ __half g_qkv16[(size_t)MTOT * QKV_COLS];   // 24 MB
__device__ __half g_attn16[(size_t)MTOT * C_];        // 8 MB
__device__ __half g_x16[(size_t)MTOT * C_];           // 8 MB
__device__ __half g_wqkv16[(size_t)QKV_COLS * C_];    // 6 MB
__device__ __half g_wproj16[(size_t)C_ * C_];         // 2 MB
__device__ float  g_la[(size_t)MTOT * 8];             // 128 KB

// ---------------------------------------------------------------------------
// helpers
// ---------------------------------------------------------------------------
__device__ __forceinline__ float ex2(float x) {
    float y;
    asm("ex2.approx.ftz.f32 %0, %1;" : "=f"(y) : "f"(x));
    return y;
}
__device__ __forceinline__ uint32_t s2u(const void* p) {
    return (uint32_t)__cvta_generic_to_shared(p);
}
__device__ __forceinline__ uint32_t sw128(uint32_t byteoff) {
    return byteoff ^ ((byteoff >> 3) & 0x70);
}
__device__ __forceinline__ void ldsm_x4(uint32_t* r, uint32_t addr) {
    asm volatile("ldmatrix.sync.aligned.m8n8.x4.shared.b16 {%0,%1,%2,%3}, [%4];"
                 : "=r"(r[0]), "=r"(r[1]), "=r"(r[2]), "=r"(r[3]) : "r"(addr));
}
__device__ __forceinline__ void ldsm_x4_t(uint32_t* r, uint32_t addr) {
    asm volatile("ldmatrix.sync.aligned.m8n8.x4.trans.shared.b16 {%0,%1,%2,%3}, [%4];"
                 : "=r"(r[0]), "=r"(r[1]), "=r"(r[2]), "=r"(r[3]) : "r"(addr));
}
__device__ __forceinline__ void mma_f16(float* c, const uint32_t* a, const uint32_t* b) {
    asm volatile("mma.sync.aligned.m16n8k16.row.col.f32.f16.f16.f32 "
                 "{%0,%1,%2,%3}, {%4,%5,%6,%7}, {%8,%9}, {%0,%1,%2,%3};"
                 : "+f"(c[0]), "+f"(c[1]), "+f"(c[2]), "+f"(c[3])
                 : "r"(a[0]), "r"(a[1]), "r"(a[2]), "r"(a[3]),
                   "r"(b[0]), "r"(b[1]));
}
__device__ __forceinline__ uint32_t h2pack(float x, float y) {
    __half2 t = __floats2half2_rn(x, y);
    return *(uint32_t*)&t;
}
__device__ __forceinline__ void cp_async16(uint32_t saddr, const void* gaddr) {
    asm volatile("cp.async.cg.shared.global [%0], [%1], 16;"
                 :: "r"(saddr), "l"(gaddr));
}
__device__ __forceinline__ void cp_commit() {
    asm volatile("cp.async.commit_group;");
}
template<int NW> __device__ __forceinline__ void cp_wait() {
    asm volatile("cp.async.wait_group %0;" :: "n"(NW));
}

// ---------------------------------------------------------------------------
// Kernel 0a: fp32 -> fp16 convert (weights)
// ---------------------------------------------------------------------------
__global__ __launch_bounds__(256) void f2h_kernel(
    const float* __restrict__ in, __half* __restrict__ out, int n4)
{
    int i = blockIdx.x * 256 + threadIdx.x;
    if (i >= n4) return;
    float4 v = *(const float4*)(in + 4 * (size_t)i);
    __half2 h0 = __floats2half2_rn(v.x, v.y);
    __half2 h1 = __floats2half2_rn(v.z, v.w);
    uint2 o; o.x = *(uint32_t*)&h0; o.y = *(uint32_t*)&h1;
    *(uint2*)(out + 4 * (size_t)i) = o;
}

// ---------------------------------------------------------------------------
// Kernel 0b: fused x convert (fp32->fp16) + LoRA activations.
// One warp per row: read x row once (float4), write x16, compute 8 lora dots.
// ---------------------------------------------------------------------------
__global__ __launch_bounds__(256) void f2h_lora_kernel(
    const float* __restrict__ x, const float* __restrict__ la_w,
    __half* __restrict__ x16, float* __restrict__ la)
{
    int warp = threadIdx.x >> 5;
    int lane = threadIdx.x & 31;
    int row  = blockIdx.x * 8 + warp;
    if (row >= MTOT) return;
    const float4* xr4 = (const float4*)(x + (size_t)row * C_);
    __half* o16 = x16 + (size_t)row * C_;
    float acc[8] = {0.f,0.f,0.f,0.f,0.f,0.f,0.f,0.f};
    #pragma unroll
    for (int k4 = lane; k4 < C_ / 4; k4 += 32) {
        float4 v = xr4[k4];
        __half2 h0 = __floats2half2_rn(v.x, v.y);
        __half2 h1 = __floats2half2_rn(v.z, v.w);
        uint2 o; o.x = *(uint32_t*)&h0; o.y = *(uint32_t*)&h1;
        *(uint2*)(o16 + 4 * k4) = o;
        int k = 4 * k4;
        #pragma unroll
        for (int r = 0; r < 8; r++) {
            const float* wr = la_w + r * C_ + k;
            acc[r] += v.x * wr[0] + v.y * wr[1] + v.z * wr[2] + v.w * wr[3];
        }
    }
    #pragma unroll
    for (int r = 0; r < 8; r++) {
        #pragma unroll
        for (int off = 16; off; off >>= 1)
            acc[r] += __shfl_xor_sync(0xffffffffu, acc[r], off);
    }
    if (lane == 0) {
        float* out = la + (size_t)row * 8;
        #pragma unroll
        for (int r = 0; r < 8; r++) out[r] = acc[r];
    }
}

// ---------------------------------------------------------------------------
// Kernel 2: fp16 tensor-core GEMM (fp32 accum), 3-stage cp.async pipeline.
// Block 128x128, BK=64 halves, SW128 smem, 8 warps (2m x 4n), warp 64x32.
// ---------------------------------------------------------------------------
#define BKH 64
#define STAGE_BYTES (128 * BKH * 2)   // 16 KB per operand per stage
#define NSTAGE 3
template <bool FUSE_LORA, bool HALF_OUT>
__global__ __launch_bounds__(256) void hgemm_kernel(
    const __half* __restrict__ A, const __half* __restrict__ W,
    const float* __restrict__ bias,
    const float* __restrict__ la, const float* __restrict__ lb,
    void* __restrict__ Cout, int M, int N, int K)
{
    extern __shared__ __half smem[];
    const uint32_t sA = s2u(smem);
    const uint32_t sB = sA + NSTAGE * STAGE_BYTES;

    const int tid  = threadIdx.x;
    const int warp = tid >> 5;
    const int lane = tid & 31;
    const int wm = warp & 1;
    const int wn = warp >> 1;
    const int brow = blockIdx.y * 128;
    const int bcol = blockIdx.x * 128;
    const int g = lane >> 3, ri = lane & 7;

    const __half* Ag = A + (size_t)brow * K;
    const __half* Wg = W + (size_t)bcol * K;

    const int lr = tid >> 3;
    const int lc = tid & 7;

    float acc[4][4][4];
    #pragma unroll
    for (int i = 0; i < 4; i++)
        #pragma unroll
        for (int j = 0; j < 4; j++)
            #pragma unroll
            for (int r = 0; r < 4; r++) acc[i][j][r] = 0.f;

    auto load_stage = [&](int st, int k0) {
        uint32_t bA = sA + st * STAGE_BYTES;
        uint32_t bB = sB + st * STAGE_BYTES;
        #pragma unroll
        for (int s = 0; s < 4; s++) {
            int row = lr + s * 32;
            uint32_t off = sw128(row * 128 + lc * 16);
            cp_async16(bA + off, Ag + (size_t)row * K + k0 + lc * 8);
            cp_async16(bB + off, Wg + (size_t)row * K + k0 + lc * 8);
        }
        cp_commit();
    };

    const int niter = K / BKH;
    load_stage(0, 0);
    if (niter > 1) load_stage(1, BKH);

    int st = 0;
    for (int it = 0; it < niter; it++) {
        if (it + 2 < niter) {
            int st2 = st + 2; if (st2 >= NSTAGE) st2 -= NSTAGE;
            load_stage(st2, (it + 2) * BKH);
            cp_wait<2>();
        } else if (it + 1 < niter) cp_wait<1>();
        else                       cp_wait<0>();
        __syncthreads();

        uint32_t bA = sA + st * STAGE_BYTES;
        uint32_t bB = sB + st * STAGE_BYTES;

        #pragma unroll
        for (int kc = 0; kc < 4; kc++) {
            uint32_t af[4][4];
            #pragma unroll
            for (int mi = 0; mi < 4; mi++) {
                int row  = wm * 64 + mi * 16 + (g & 1) * 8 + ri;
                int colb = kc * 32 + (g >> 1) * 16;
                ldsm_x4(af[mi], bA + sw128(row * 128 + colb));
            }
            uint32_t bf[4][2];
            #pragma unroll
            for (int np = 0; np < 2; np++) {
                uint32_t t[4];
                int row  = wn * 32 + np * 16 + (g >> 1) * 8 + ri;
                int colb = kc * 32 + (g & 1) * 16;
                ldsm_x4(t, bB + sw128(row * 128 + colb));
                bf[2 * np][0] = t[0];     bf[2 * np][1] = t[1];
                bf[2 * np + 1][0] = t[2]; bf[2 * np + 1][1] = t[3];
            }
            #pragma unroll
            for (int mi = 0; mi < 4; mi++)
                #pragma unroll
                for (int ni = 0; ni < 4; ni++)
                    mma_f16(acc[mi][ni], af[mi], bf[ni]);
        }
        __syncthreads();
        if (++st == NSTAGE) st = 0;
    }

    // epilogue
    const int r4 = lane >> 2;
    const int c4 = lane & 3;
    bool do_q = false, do_v = false;
    if (FUSE_LORA) { do_q = (bcol < C_); do_v = (bcol >= 2 * C_); }

    #pragma unroll
    for (int mi = 0; mi < 4; mi++) {
        int m1 = brow + wm * 64 + mi * 16 + r4;
        float laA[4] = {0,0,0,0}, laB[4] = {0,0,0,0};
        if (FUSE_LORA && (do_q || do_v)) {
            int off = do_q ? 0 : 4;
            const float* l1 = la + (size_t)m1 * 8 + off;
            const float* l2 = la + (size_t)(m1 + 8) * 8 + off;
            #pragma unroll
            for (int r = 0; r < 4; r++) { laA[r] = l1[r]; laB[r] = l2[r]; }
        }
        #pragma unroll
        for (int ni = 0; ni < 4; ni++) {
            int n1 = bcol + wn * 32 + ni * 8 + 2 * c4;
            float b0 = bias[n1], b1 = bias[n1 + 1];
            float d00 = 0.f, d01 = 0.f, d10 = 0.f, d11 = 0.f;
            if (FUSE_LORA && (do_q || do_v)) {
                int o0 = do_q ? n1 : (C_ + (n1 - 2 * C_));
                const float* lb0 = lb + (size_t)o0 * LORA_R;
                const float* lb1 = lb0 + LORA_R;
                #pragma unroll
                for (int r = 0; r < 4; r++) {
                    d00 += laA[r] * lb0[r];  d01 += laA[r] * lb1[r];
                    d10 += laB[r] * lb0[r];  d11 += laB[r] * lb1[r];
                }
                d00 *= LORA_SCALE; d01 *= LORA_SCALE;
                d10 *= LORA_SCALE; d11 *= LORA_SCALE;
            }
            float v00 = acc[mi][ni][0] + b0 + d00;
            float v01 = acc[mi][ni][1] + b1 + d01;
            float v10 = acc[mi][ni][2] + b0 + d10;
            float v11 = acc[mi][ni][3] + b1 + d11;
            if (HALF_OUT) {
                __half* Ch = (__half*)Cout;
                *(__half2*)(Ch + (size_t)m1 * N + n1)       = __floats2half2_rn(v00, v01);
                *(__half2*)(Ch + (size_t)(m1 + 8) * N + n1) = __floats2half2_rn(v10, v11);
            } else {
                float* Cf = (float*)Cout;
                *(float2*)(Cf + (size_t)m1 * N + n1)       = make_float2(v00, v01);
                *(float2*)(Cf + (size_t)(m1 + 8) * N + n1) = make_float2(v10, v11);
            }
        }
    }
}

// ---------------------------------------------------------------------------
// Kernel 3: tensor-core flash attention, cp.async double-buffered K/V.
// Dynamic smem: Qs [128*SKW] | Ks[2][64*SKW] | Vs[2][64*SKW] halves.
// ---------------------------------------------------------------------------
#define SKW 72
#define KVST (64 * SKW)               // halves per K/V stage
#define ATTN_SMEM ((128 * SKW + 4 * KVST) * 2)   // 55,296 bytes
__global__ __launch_bounds__(128) void attn_mma_kernel(
    const __half* __restrict__ qkv, __half* __restrict__ out)
{
    extern __shared__ __half smem[];
    __half* Qs = smem;
    __half* Ksb = smem + 128 * SKW;
    __half* Vsb = Ksb + 2 * KVST;

    const int bh = blockIdx.y, b = bh >> 4, h = bh & 15;
    const int q0 = blockIdx.x * 128;
    const int tid = threadIdx.x, warp = tid >> 5, lane = tid & 31;
    const int g = lane >> 3, ri = lane & 7;
    const float cexp = 0.18033688f;    // 0.125 * log2(e)

    // K/V tile loader via cp.async (one stage, one commit)
    auto load_kv = [&](int st, int kt) {
        uint32_t bK = s2u(Ksb + st * KVST);
        uint32_t bV = s2u(Vsb + st * KVST);
        #pragma unroll
        for (int rep = 0; rep < 4; rep++) {
            int it = tid + rep * 128;          // 0..511
            int j = it >> 3, s = it & 7;
            const __half* base = qkv + ((size_t)(b * N_ + kt * 64 + j) * QKV_COLS)
                                 + C_ + h * HD_ + s * 8;
            uint32_t off = (j * SKW + s * 8) * 2;
            cp_async16(bK + off, base);
            cp_async16(bV + off, base + C_);
        }
        cp_commit();
    };

    load_kv(0, 0);   // prefetch tile 0 before Q staging

    // Q tile -> smem
    for (int it = tid; it < 128 * 8; it += 128) {
        int r = it >> 3, s = it & 7;
        *(uint4*)&Qs[r * SKW + s * 8] =
            *((const uint4*)(qkv + ((size_t)(b * N_ + q0 + r) * QKV_COLS) + h * HD_) + s);
    }
    __syncthreads();

    uint32_t qf[2][4][4];
    {
        int rb = warp * 32;
        #pragma unroll
        for (int mt = 0; mt < 2; mt++)
            #pragma unroll
            for (int kc = 0; kc < 4; kc++) {
                int row = rb + mt * 16 + (g & 1) * 8 + ri;
                int col = kc * 16 + (g >> 1) * 8;
                ldsm_x4(qf[mt][kc], s2u(&Qs[row * SKW + col]));
            }
    }

    float of[2][8][4];
    #pragma unroll
    for (int mt = 0; mt < 2; mt++)
        #pragma unroll
        for (int dt = 0; dt < 8; dt++)
            #pragma unroll
            for (int r = 0; r < 4; r++) of[mt][dt][r] = 0.f;
    float mrow[2][2] = {{-1e30f, -1e30f}, {-1e30f, -1e30f}};
    float lrow[2][2] = {{0.f, 0.f}, {0.f, 0.f}};

    const int ntiles = N_ / 64;
    for (int kt = 0; kt < ntiles; kt++) {
        if (kt + 1 < ntiles) { load_kv((kt + 1) & 1, kt + 1); cp_wait<1>(); }
        else                   cp_wait<0>();
        __syncthreads();

        const __half* Ks = Ksb + (kt & 1) * KVST;
        const __half* Vs = Vsb + (kt & 1) * KVST;

        float sc[2][8][4];
        #pragma unroll
        for (int mt = 0; mt < 2; mt++)
            #pragma unroll
            for (int nt = 0; nt < 8; nt++)
                #pragma unroll
                for (int r = 0; r < 4; r++) sc[mt][nt][r] = 0.f;

        #pragma unroll
        for (int kc = 0; kc < 4; kc++) {
            uint32_t bf[8][2];
            #pragma unroll
            for (int np = 0; np < 4; np++) {
                uint32_t t[4];
                int row = np * 16 + (g >> 1) * 8 + ri;
                int col = kc * 16 + (g & 1) * 8;
                ldsm_x4(t, s2u(&Ks[row * SKW + col]));
                bf[2 * np][0] = t[0];     bf[2 * np][1] = t[1];
                bf[2 * np + 1][0] = t[2]; bf[2 * np + 1][1] = t[3];
            }
            #pragma unroll
            for (int mt = 0; mt < 2; mt++)
                #pragma unroll
                for (int nt = 0; nt < 8; nt++)
                    mma_f16(sc[mt][nt], qf[mt][kc], bf[nt]);
        }

        #pragma unroll
        for (int mt = 0; mt < 2; mt++)
            #pragma unroll
            for (int sub = 0; sub < 2; sub++) {
                float tm = -1e30f;
                #pragma unroll
                for (int nt = 0; nt < 8; nt++)
                    tm = fmaxf(tm, fmaxf(sc[mt][nt][2 * sub], sc[mt][nt][2 * sub + 1]));
                tm = fmaxf(tm, __shfl_xor_sync(0xffffffffu, tm, 1));
                tm = fmaxf(tm, __shfl_xor_sync(0xffffffffu, tm, 2));
                float mnew = fmaxf(mrow[mt][sub], tm);
                float corr = ex2((mrow[mt][sub] - mnew) * cexp);
                mrow[mt][sub] = mnew;
                lrow[mt][sub] *= corr;
                #pragma unroll
                for (int dt = 0; dt < 8; dt++) {
                    of[mt][dt][2 * sub]     *= corr;
                    of[mt][dt][2 * sub + 1] *= corr;
                }
                float lp = 0.f;
                #pragma unroll
                for (int nt = 0; nt < 8; nt++) {
                    float p0 = ex2((sc[mt][nt][2 * sub]     - mnew) * cexp);
                    float p1 = ex2((sc[mt][nt][2 * sub + 1] - mnew) * cexp);
                    sc[mt][nt][2 * sub] = p0; sc[mt][nt][2 * sub + 1] = p1;
                    lp += p0 + p1;
                }
                lrow[mt][sub] += lp;
            }

        #pragma unroll
        for (int kc = 0; kc < 4; kc++) {
            uint32_t pa[2][4];
            #pragma unroll
            for (int mt = 0; mt < 2; mt++) {
                pa[mt][0] = h2pack(sc[mt][2 * kc][0],     sc[mt][2 * kc][1]);
                pa[mt][1] = h2pack(sc[mt][2 * kc][2],     sc[mt][2 * kc][3]);
                pa[mt][2] = h2pack(sc[mt][2 * kc + 1][0], sc[mt][2 * kc + 1][1]);
                pa[mt][3] = h2pack(sc[mt][2 * kc + 1][2], sc[mt][2 * kc + 1][3]);
            }
            uint32_t vb[8][2];
            #pragma unroll
            for (int dp = 0; dp < 4; dp++) {
                uint32_t t[4];
                int row = kc * 16 + (g & 1) * 8 + ri;
                int col = dp * 16 + (g >> 1) * 8;
                ldsm_x4_t(t, s2u(&Vs[row * SKW + col]));
                vb[2 * dp][0] = t[0];     vb[2 * dp][1] = t[1];
                vb[2 * dp + 1][0] = t[2]; vb[2 * dp + 1][1] = t[3];
            }
            #pragma unroll
            for (int mt = 0; mt < 2; mt++)
                #pragma unroll
                for (int dt = 0; dt < 8; dt++)
                    mma_f16(of[mt][dt], pa[mt], vb[dt]);
        }
        __syncthreads();
    }

    #pragma unroll
    for (int mt = 0; mt < 2; mt++)
        #pragma unroll
        for (int sub = 0; sub < 2; sub++) {
            float l = lrow[mt][sub];
            l += __shfl_xor_sync(0xffffffffu, l, 1);
            l += __shfl_xor_sync(0xffffffffu, l, 2);
            float inv = 1.f / l;
            int r = q0 + warp * 32 + mt * 16 + (lane >> 2) + sub * 8;
            __half* op = out + ((size_t)(b * N_ + r) * C_) + h * HD_ + 2 * (lane & 3);
            #pragma unroll
            for (int dt = 0; dt < 8; dt++) {
                *(__half2*)(op + dt * 8) =
                    __floats2half2_rn(of[mt][dt][2 * sub] * inv,
                                      of[mt][dt][2 * sub + 1] * inv);
            }
        }
}

// ---------------------------------------------------------------------------
// host launch
// ---------------------------------------------------------------------------
extern "C" void kernel_launch(void* const* d_in, const int* in_sizes, int n_in,
                              void* d_out, int out_size)
{
    const float* x      = (const float*)d_in[0];
    const float* W_qkv  = (const float*)d_in[1];
    const float* b_qkv  = (const float*)d_in[2];
    const float* lora_A = (const float*)d_in[3];
    const float* lora_B = (const float*)d_in[4];
    const float* W_proj = (const float*)d_in[5];
    const float* b_proj = (const float*)d_in[6];
    float* out = (float*)d_out;

    void* p;
    cudaGetSymbolAddress(&p, g_qkv16);   __half* qkv16   = (__half*)p;
    cudaGetSymbolAddress(&p, g_attn16);  __half* attn16  = (__half*)p;
    cudaGetSymbolAddress(&p, g_x16);     __half* x16     = (__half*)p;
    cudaGetSymbolAddress(&p, g_wqkv16);  __half* wqkv16  = (__half*)p;
    cudaGetSymbolAddress(&p, g_wproj16); __half* wproj16 = (__half*)p;
    cudaGetSymbolAddress(&p, g_la);      float*  la      = (float*)p;

    const int GEMM_SMEM = 2 * NSTAGE * STAGE_BYTES;   // 96 KB
    cudaFuncSetAttribute(hgemm_kernel<true,  true>,
                         cudaFuncAttributeMaxDynamicSharedMemorySize, GEMM_SMEM);
    cudaFuncSetAttribute(hgemm_kernel<false, false>,
                         cudaFuncAttributeMaxDynamicSharedMemorySize, GEMM_SMEM);
    cudaFuncSetAttribute(attn_mma_kernel,
                         cudaFuncAttributeMaxDynamicSharedMemorySize, ATTN_SMEM);

    // 0. converts + fused lora_a
    f2h_lora_kernel<<<MTOT / 8, 256>>>(x, lora_A, x16, la);
    f2h_kernel<<<(QKV_COLS * C_ / 4 + 255) / 256, 256>>>(W_qkv, wqkv16, QKV_COLS * C_ / 4);
    f2h_kernel<<<(C_ * C_ / 4 + 255) / 256, 256>>>(W_proj, wproj16, C_ * C_ / 4);

    // 1. fused QKV GEMM + bias + LoRA delta -> fp16
    {
        dim3 grid(QKV_COLS / 128, MTOT / 128);
        hgemm_kernel<true, true><<<grid, 256, GEMM_SMEM>>>(
            x16, wqkv16, b_qkv, la, lora_B, qkv16, MTOT, QKV_COLS, C_);
    }

    // 2. flash attention (double-buffered K/V) -> fp16
    {
        dim3 grid(N_ / 128, B_ * H_);
        attn_mma_kernel<<<grid, 128, ATTN_SMEM>>>(qkv16, attn16);
    }

    // 3. output projection (fp16 mma, fp32 out)
    {
        dim3 grid(C_ / 128, MTOT / 128);
        hgemm_kernel<false, false><<<grid, 256, GEMM_SMEM>>>(
            attn16, wproj16, b_proj, nullptr, nullptr, out, MTOT, C_, C_);
    }
}